// round 1
// baseline (speedup 1.0000x reference)
#include <cuda_runtime.h>

// KroneckerAddress: B=64 rows, U=3 parts of DP=128, K=32.
// addr[b, i*128*128 + j*128 + k] = softmax(z0)[i] * softmax(z1)[j] * softmax(z2)[k]
// Return top-32 (indices, weights) per row. Output layout: [indices(64*32) as float | weights(64*32)].
//
// Pruning: global top-32 element must be top-32 per part, and with parts sorted
// descending, rank triple (i,j,k) (1-indexed) needs i*j*k <= 32 -> exactly 300 candidates.

#define BB 64
#define UU 3
#define DP 128
#define KK 32
#define NCAND_MAX 512

__global__ __launch_bounds__(128, 8)
void kron_topk_kernel(const float* __restrict__ z,
                      const float* __restrict__ log_tau,
                      float* __restrict__ out,
                      int wofs)
{
    const int b = blockIdx.x;
    const int t = threadIdx.x;           // 0..127
    const int lane = t & 31;
    const int wid  = t >> 5;             // 4 warps

    __shared__ float p[UU][DP];          // softmax probs
    __shared__ float tv[UU][KK];         // per-part top-32 values (sorted desc)
    __shared__ int   ti[UU][KK];         // per-part top-32 original indices
    __shared__ float red[4];
    __shared__ float cv[NCAND_MAX];      // candidate products
    __shared__ int   cg[NCAND_MAX];      // candidate global indices
    __shared__ int   ccount;

    const float inv_tau = 1.0f / expf(log_tau[0]);

    // ---- softmax per part (one thread per element) ----
    const float* zrow = z + (size_t)b * (UU * DP);
    #pragma unroll
    for (int u = 0; u < UU; u++) {
        float x = zrow[u * DP + t] * inv_tau;

        // block max
        float m = x;
        #pragma unroll
        for (int o = 16; o > 0; o >>= 1)
            m = fmaxf(m, __shfl_xor_sync(0xFFFFFFFFu, m, o));
        if (lane == 0) red[wid] = m;
        __syncthreads();
        m = fmaxf(fmaxf(red[0], red[1]), fmaxf(red[2], red[3]));
        __syncthreads();

        float e = expf(x - m);

        // block sum
        float s = e;
        #pragma unroll
        for (int o = 16; o > 0; o >>= 1)
            s += __shfl_xor_sync(0xFFFFFFFFu, s, o);
        if (lane == 0) red[wid] = s;
        __syncthreads();
        s = (red[0] + red[1]) + (red[2] + red[3]);

        p[u][t] = e / s;
        __syncthreads();
    }

    // ---- per-part top-32 via rank counting (sorted descending, tie -> lower index) ----
    #pragma unroll
    for (int u = 0; u < UU; u++) {
        float myv = p[u][t];
        int r = 0;
        #pragma unroll 8
        for (int j = 0; j < DP; j++) {
            float vj = p[u][j];
            r += (int)((vj > myv) | ((vj == myv) & (j < t)));
        }
        if (r < KK) { tv[u][r] = myv; ti[u][r] = t; }
    }
    if (t == 0) ccount = 0;
    __syncthreads();

    // ---- enumerate candidates with (i+1)(j+1)(k+1) <= 32 (exactly 300 triples) ----
    if (t < KK) {
        const int i = t;
        const float vi = tv[0][i];
        const int  gi = ti[0][i] * (DP * DP);
        const int limj = KK / (i + 1);
        for (int j = 0; j < limj; j++) {
            const float vij = vi * tv[1][j];
            const int  gij = gi + ti[1][j] * DP;
            const int limk = KK / ((i + 1) * (j + 1));
            for (int k = 0; k < limk; k++) {
                int pos = atomicAdd(&ccount, 1);
                cv[pos] = vij * tv[2][k];
                cg[pos] = gij + ti[2][k];
            }
        }
    }
    __syncthreads();

    const int nc = ccount;   // 300

    // ---- global rank of each candidate; emit top-32 ----
    for (int c = t; c < nc; c += blockDim.x) {
        const float vc = cv[c];
        const int   gc = cg[c];
        int r = 0;
        for (int d = 0; d < nc; d++) {
            float vd = cv[d];
            r += (int)((vd > vc) | ((vd == vc) & (cg[d] < gc)));
        }
        if (r < KK) {
            out[b * KK + r]        = (float)gc;   // indices (exact in fp32: < 2^21)
            out[wofs + b * KK + r] = vc;          // weights
        }
    }
}

extern "C" void kernel_launch(void* const* d_in, const int* in_sizes, int n_in,
                              void* d_out, int out_size)
{
    const float* z       = (const float*)d_in[0];
    const float* log_tau = (const float*)d_in[1];
    float* out = (float*)d_out;
    kron_topk_kernel<<<BB, 128>>>(z, log_tau, out, out_size / 2);
}

// round 2
// speedup vs baseline: 2.2975x; 2.2975x over previous
#include <cuda_runtime.h>

// KroneckerAddress: B=64 rows, U=3 parts of DP=128, K=32.
// Top-32 of softmax(z0) x softmax(z1) x softmax(z2) (Kronecker), per row.
// Output: [indices(64*32) as float | weights(64*32)].
//
// Candidate pruning: with each part's top-32 sorted descending, a rank triple
// (i,j,k) (1-indexed) can be in the global top-32 only if i*j*k <= 32
// -> exactly 300 candidates. Slots are statically addressed (no atomics).

#define BB 64
#define DP 128
#define KK 32
#define NC 300      // sum_{n<=32} d3(n)
#define NPAIR 119   // sum_{n<=32} d2(n)

// Pair-index prefix: POFF[i] = sum_{i'<i} floor(32/(i'+1))
__constant__ int POFF[32] = {
    0,32,48,58,66,72,77,81,85,88,91,93,95,97,99,101,
    103,104,105,106,107,108,109,110,111,112,113,114,115,116,117,118};
// Candidate prefix: OFF[i] = #candidates with first factor rank < i
__constant__ int OFF[32] = {
    0,119,169,196,216,230,240,248,256,261,266,269,272,275,278,281,
    284,285,286,287,288,289,290,291,292,293,294,295,296,297,298,299};
// T32[n] = floor(32/n), n=1..32
__constant__ int T32[33] = {
    0,32,16,10,8,6,5,4,4,3,3,2,2,2,2,2,2,
    1,1,1,1,1,1,1,1,1,1,1,1,1,1,1,1};

__global__ __launch_bounds__(384, 3)
void kron_topk_kernel(const float* __restrict__ z,
                      const float* __restrict__ log_tau,
                      float* __restrict__ out,
                      int wofs)
{
    const int b   = blockIdx.x;
    const int t   = threadIdx.x;        // 0..383
    const int g   = t >> 7;             // part 0..2
    const int lt  = t & 127;            // index within part
    const int w   = t >> 5;             // warp 0..11
    const int lane = t & 31;

    __shared__ float esh[3][DP];        // unnormalized exp values
    __shared__ float tvv[3][KK];        // per-part top-32 values, desc
    __shared__ int   tii[3][KK];        // per-part top-32 original indices
    __shared__ float redA[12], redB[12];
    __shared__ float Ssh[3];            // per-part exp sums
    __shared__ unsigned long long kv[NC];

    const float inv_tau = __expf(-log_tau[0]);

    // ---- softmax (unnormalized) — all 3 parts concurrently ----
    float x = z[(size_t)b * (3 * DP) + t] * inv_tau;

    float m = x;
    #pragma unroll
    for (int o = 16; o > 0; o >>= 1)
        m = fmaxf(m, __shfl_xor_sync(0xFFFFFFFFu, m, o));
    if (lane == 0) redA[w] = m;
    __syncthreads();
    m = fmaxf(fmaxf(redA[g*4+0], redA[g*4+1]), fmaxf(redA[g*4+2], redA[g*4+3]));

    float e = __expf(x - m);
    esh[g][lt] = e;

    float s = e;
    #pragma unroll
    for (int o = 16; o > 0; o >>= 1)
        s += __shfl_xor_sync(0xFFFFFFFFu, s, o);
    if (lane == 0) redB[w] = s;
    __syncthreads();
    if (lt == 0)
        Ssh[g] = (redB[g*4+0] + redB[g*4+1]) + (redB[g*4+2] + redB[g*4+3]);

    // ---- per-part top-32 via rank counting (concurrent across parts) ----
    {
        const float myv = e;
        int r = 0;
        #pragma unroll 8
        for (int j = 0; j < DP; j++) {
            float vj = esh[g][j];
            r += (int)((vj > myv) | ((vj == myv) & (j < lt)));
        }
        if (r < KK) { tvv[g][r] = myv; tii[g][r] = lt; }
    }
    __syncthreads();

    // ---- enumerate the 300 candidates: one thread per (i,j) pair ----
    if (t < NPAIR) {
        // find i: POFF[i] <= t < POFF[i+1]
        int i = 0;
        #pragma unroll
        for (int q = 1; q < 32; q++) i += (int)(POFF[q] <= t);
        const int j = t - POFF[i];
        int off = OFF[i];
        for (int jj = 0; jj < j; jj++) off += T32[(i + 1) * (jj + 1)];
        const int limk = T32[(i + 1) * (j + 1)];

        const float vij = tvv[0][i] * tvv[1][j];
        const int   gij = tii[0][i] * (DP * DP) + tii[1][j] * DP;
        for (int k = 0; k < limk; k++) {
            const float v = vij * tvv[2][k];
            const unsigned int gidx = (unsigned int)(gij + tii[2][k]);
            kv[off + k] = ((unsigned long long)__float_as_uint(v) << 32)
                        | (unsigned long long)(~gidx);
        }
    }
    __syncthreads();

    // ---- global rank of each candidate; emit top-32 ----
    if (t < NC) {
        const unsigned long long mykey = kv[t];
        int r = 0;
        #pragma unroll 4
        for (int d = 0; d < NC; d++)
            r += (int)(kv[d] > mykey);
        if (r < KK) {
            const unsigned int gidx = ~(unsigned int)mykey;
            const float v = __uint_as_float((unsigned int)(mykey >> 32));
            const float invS = 1.0f / (Ssh[0] * Ssh[1] * Ssh[2]);
            out[b * KK + r]        = (float)gidx;
            out[wofs + b * KK + r] = v * invS;
        }
    }
}

extern "C" void kernel_launch(void* const* d_in, const int* in_sizes, int n_in,
                              void* d_out, int out_size)
{
    const float* z       = (const float*)d_in[0];
    const float* log_tau = (const float*)d_in[1];
    float* out = (float*)d_out;
    kron_topk_kernel<<<BB, 384>>>(z, log_tau, out, out_size / 2);
}